// round 12
// baseline (speedup 1.0000x reference)
#include <cuda_runtime.h>
#include <cstdint>

#define NUM_IN 25
#define NUM_OUT 20
#define J_PAIRS 13

typedef unsigned long long u64;

// Constant bank: all packed weights (constant port / LDC only).
struct __align__(16) CParams {
    u64 w1[25][14];  // [k][jp] = {W1[2jp][k], W1[2jp+1][k]}
    u64 b1[14];
    u64 w2[25][10];  // [k][ip] = {W2[2ip][k], W2[2ip+1][k]}
    u64 b2[10];
};
__constant__ CParams cP;
__device__ CParams dScratch;

__device__ __forceinline__ u64 dpack(float lo, float hi) {
    return (u64)__float_as_uint(lo) | ((u64)__float_as_uint(hi) << 32);
}
__device__ __forceinline__ u64 pk2s(float v) {
    u64 r;
    asm("mov.b64 %0, {%1, %1};" : "=l"(r) : "f"(v));
    return r;
}
__device__ __forceinline__ void upk2(u64 v, float& lo, float& hi) {
    asm("mov.b64 {%0, %1}, %2;" : "=f"(lo), "=f"(hi) : "l"(v));
}
__device__ __forceinline__ u64 ffma2(u64 a, u64 b, u64 c) {
    u64 d;
    asm("fma.rn.f32x2 %0, %1, %2, %3;" : "=l"(d) : "l"(a), "l"(b), "l"(c));
    return d;
}

__global__ void prep_kernel(const float* __restrict__ W1, const float* __restrict__ b1,
                            const float* __restrict__ W2, const float* __restrict__ b2)
{
    int t = blockIdx.x * blockDim.x + threadIdx.x;
    int stride = gridDim.x * blockDim.x;
    for (int i = t; i < 25 * 14; i += stride) {
        int k = i / 14, jp = i % 14;
        float lo = 0.0f, hi = 0.0f;
        if (jp < J_PAIRS) {
            lo = W1[(2 * jp) * NUM_IN + k];
            if (2 * jp + 1 < NUM_IN) hi = W1[(2 * jp + 1) * NUM_IN + k];
        }
        dScratch.w1[k][jp] = dpack(lo, hi);
    }
    for (int i = t; i < 14; i += stride) {
        float lo = 0.0f, hi = 0.0f;
        if (i < J_PAIRS) {
            lo = b1[2 * i];
            if (2 * i + 1 < NUM_IN) hi = b1[2 * i + 1];
        }
        dScratch.b1[i] = dpack(lo, hi);
    }
    for (int i = t; i < 25 * 10; i += stride) {
        int k = i / 10, ip = i % 10;
        dScratch.w2[k][ip] = dpack(W2[(2 * ip) * NUM_IN + k], W2[(2 * ip + 1) * NUM_IN + k]);
    }
    for (int i = t; i < 10; i += stride)
        dScratch.b2[i] = dpack(b2[2 * i], b2[2 * i + 1]);
}

// Layer-1 partial over k in [K0,K1)
template <int K0, int K1>
__device__ __forceinline__ void l1_phase(const float (&xa0)[K1 - K0],
                                         const float (&xa1)[K1 - K0],
                                         u64 (&acc0)[J_PAIRS], u64 (&acc1)[J_PAIRS])
{
    #pragma unroll
    for (int k = K0; k < K1; k++) {
        u64 xk0 = pk2s(xa0[k - K0]);
        u64 xk1 = pk2s(xa1[k - K0]);
        const ulonglong2* wv = reinterpret_cast<const ulonglong2*>(cP.w1[k]);
        #pragma unroll
        for (int q = 0; q < 6; q++) {
            ulonglong2 w = wv[q];
            acc0[2 * q]     = ffma2(w.x, xk0, acc0[2 * q]);
            acc1[2 * q]     = ffma2(w.x, xk1, acc1[2 * q]);
            acc0[2 * q + 1] = ffma2(w.y, xk0, acc0[2 * q + 1]);
            acc1[2 * q + 1] = ffma2(w.y, xk1, acc1[2 * q + 1]);
        }
        u64 w12 = cP.w1[k][12];
        acc0[12] = ffma2(w12, xk0, acc0[12]);
        acc1[12] = ffma2(w12, xk1, acc1[12]);
    }
}

// Layer-2 chunk over vec-pair range [Q0,Q1): output rows 4*Q0 .. 4*Q1-1.
// All weights via constant port.
template <int Q0, int Q1>
__device__ __forceinline__ void l2_chunk(const float (&y0)[26], const float (&y1)[26],
                                         float (&zl)[4 * (Q1 - Q0)], float (&zh)[4 * (Q1 - Q0)])
{
    constexpr int NP = 2 * (Q1 - Q0);
    u64 z0[NP], z1[NP];
    {
        const ulonglong2* bv = reinterpret_cast<const ulonglong2*>(cP.b2);
        #pragma unroll
        for (int q = Q0; q < Q1; q++) {
            ulonglong2 b = bv[q];
            z0[2 * (q - Q0)]     = b.x; z1[2 * (q - Q0)]     = b.x;
            z0[2 * (q - Q0) + 1] = b.y; z1[2 * (q - Q0) + 1] = b.y;
        }
    }
    #pragma unroll
    for (int k = 0; k < NUM_IN; k++) {
        u64 yk0 = pk2s(y0[k]);
        u64 yk1 = pk2s(y1[k]);
        #pragma unroll
        for (int q = Q0; q < Q1; q++) {
            ulonglong2 w = *reinterpret_cast<const ulonglong2*>(&cP.w2[k][2 * q]);
            z0[2 * (q - Q0)]     = ffma2(w.x, yk0, z0[2 * (q - Q0)]);
            z1[2 * (q - Q0)]     = ffma2(w.x, yk1, z1[2 * (q - Q0)]);
            z0[2 * (q - Q0) + 1] = ffma2(w.y, yk0, z0[2 * (q - Q0) + 1]);
            z1[2 * (q - Q0) + 1] = ffma2(w.y, yk1, z1[2 * (q - Q0) + 1]);
        }
    }
    #pragma unroll
    for (int p = 0; p < NP; p++) {
        float lo, hi;
        upk2(z0[p], lo, hi);
        zl[2 * p]     = fmaxf(lo, 0.0f);
        zl[2 * p + 1] = fmaxf(hi, 0.0f);
        upk2(z1[p], lo, hi);
        zh[2 * p]     = fmaxf(lo, 0.0f);
        zh[2 * p + 1] = fmaxf(hi, 0.0f);
    }
}

__global__ void __launch_bounds__(128, 6)
edge_mlp_kernel(const float* __restrict__ r,
                const float* __restrict__ a_data,
                const float* __restrict__ a_material,
                const float* __restrict__ a_influx,
                const float* __restrict__ b_data,
                const float* __restrict__ b_material,
                const float* __restrict__ b_influx,
                const float* __restrict__ e_data,
                float* __restrict__ out,
                int E)
{
    long pair = (long)blockIdx.x * blockDim.x + threadIdx.x;
    long e0 = pair * 2;
    if (e0 >= E) return;
    bool have_e1 = (e0 + 1 < E);
    long e1 = have_e1 ? (e0 + 1) : e0;

    const float4* ad4 = reinterpret_cast<const float4*>(a_data);
    const float4* bd4 = reinterpret_cast<const float4*>(b_data);
    const float4* ed4 = reinterpret_cast<const float4*>(e_data);

    u64 acc0[J_PAIRS], acc1[J_PAIRS];
    #pragma unroll
    for (int p = 0; p < J_PAIRS; p++) { acc0[p] = cP.b1[p]; acc1[p] = cP.b1[p]; }

    // Phase A1: feats 0..8 (r + a_data)
    {
        float xa0[9], xa1[9];
        xa0[0] = r[e0]; xa1[0] = r[e1];
        float4 p = ad4[2 * e0], q = ad4[2 * e1];
        xa0[1] = p.x; xa0[2] = p.y; xa0[3] = p.z; xa0[4] = p.w;
        xa1[1] = q.x; xa1[2] = q.y; xa1[3] = q.z; xa1[4] = q.w;
        p = ad4[2 * e0 + 1]; q = ad4[2 * e1 + 1];
        xa0[5] = p.x; xa0[6] = p.y; xa0[7] = p.z; xa0[8] = p.w;
        xa1[5] = q.x; xa1[6] = q.y; xa1[7] = q.z; xa1[8] = q.w;
        l1_phase<0, 9>(xa0, xa1, acc0, acc1);
    }
    // Phase A2: feats 9,10
    {
        float xa0[2], xa1[2];
        xa0[0] = a_material[e0]; xa1[0] = a_material[e1];
        xa0[1] = a_influx[e0];   xa1[1] = a_influx[e1];
        l1_phase<9, 11>(xa0, xa1, acc0, acc1);
    }
    // Phase B1: feats 11..18 (b_data)
    {
        float xb0[8], xb1[8];
        float4 p = bd4[2 * e0], q = bd4[2 * e1];
        xb0[0] = p.x; xb0[1] = p.y; xb0[2] = p.z; xb0[3] = p.w;
        xb1[0] = q.x; xb1[1] = q.y; xb1[2] = q.z; xb1[3] = q.w;
        p = bd4[2 * e0 + 1]; q = bd4[2 * e1 + 1];
        xb0[4] = p.x; xb0[5] = p.y; xb0[6] = p.z; xb0[7] = p.w;
        xb1[4] = q.x; xb1[5] = q.y; xb1[6] = q.z; xb1[7] = q.w;
        l1_phase<11, 19>(xb0, xb1, acc0, acc1);
    }
    // Phase B2: feats 19,20
    {
        float xb0[2], xb1[2];
        xb0[0] = b_material[e0]; xb1[0] = b_material[e1];
        xb0[1] = b_influx[e0];   xb1[1] = b_influx[e1];
        l1_phase<19, 21>(xb0, xb1, acc0, acc1);
    }
    // Phase B3: feats 21..24 (e_data)
    {
        float xe0[4], xe1[4];
        float4 p = ed4[e0], q = ed4[e1];
        xe0[0] = p.x; xe0[1] = p.y; xe0[2] = p.z; xe0[3] = p.w;
        xe1[0] = q.x; xe1[1] = q.y; xe1[2] = q.z; xe1[3] = q.w;
        l1_phase<21, 25>(xe0, xe1, acc0, acc1);
    }

    // ReLU -> y
    float y0[26], y1[26];
    #pragma unroll
    for (int p = 0; p < J_PAIRS; p++) {
        float lo, hi;
        upk2(acc0[p], lo, hi);
        y0[2 * p]     = fmaxf(lo, 0.0f);
        y0[2 * p + 1] = fmaxf(hi, 0.0f);
        upk2(acc1[p], lo, hi);
        y1[2 * p]     = fmaxf(lo, 0.0f);
        y1[2 * p + 1] = fmaxf(hi, 0.0f);
    }

    float4* ov = reinterpret_cast<float4*>(out);
    long Ef4_b1 = 2L * (long)E;
    long Ef4_b2 = 4L * (long)E;

    // Chunk A: rows 0..7 -> block 0
    {
        float zl[8], zh[8];
        l2_chunk<0, 2>(y0, y1, zl, zh);
        ov[2 * e0]     = make_float4(zl[0], zl[1], zl[2], zl[3]);
        ov[2 * e0 + 1] = make_float4(zl[4], zl[5], zl[6], zl[7]);
        if (have_e1) {
            ov[2 * e1]     = make_float4(zh[0], zh[1], zh[2], zh[3]);
            ov[2 * e1 + 1] = make_float4(zh[4], zh[5], zh[6], zh[7]);
        }
    }
    // Chunk B: rows 8..15 -> block 1
    {
        float zl[8], zh[8];
        l2_chunk<2, 4>(y0, y1, zl, zh);
        ov[Ef4_b1 + 2 * e0]     = make_float4(zl[0], zl[1], zl[2], zl[3]);
        ov[Ef4_b1 + 2 * e0 + 1] = make_float4(zl[4], zl[5], zl[6], zl[7]);
        if (have_e1) {
            ov[Ef4_b1 + 2 * e1]     = make_float4(zh[0], zh[1], zh[2], zh[3]);
            ov[Ef4_b1 + 2 * e1 + 1] = make_float4(zh[4], zh[5], zh[6], zh[7]);
        }
    }
    // Chunk C: rows 16..19 -> block 2
    {
        float zl[4], zh[4];
        l2_chunk<4, 5>(y0, y1, zl, zh);
        ov[Ef4_b2 + e0] = make_float4(zl[0], zl[1], zl[2], zl[3]);
        if (have_e1)
            ov[Ef4_b2 + e1] = make_float4(zh[0], zh[1], zh[2], zh[3]);
    }
}

extern "C" void kernel_launch(void* const* d_in, const int* in_sizes, int n_in,
                              void* d_out, int out_size)
{
    const float* r          = (const float*)d_in[0];
    const float* a_data     = (const float*)d_in[1];
    const float* a_material = (const float*)d_in[2];
    const float* a_influx   = (const float*)d_in[3];
    const float* b_data     = (const float*)d_in[4];
    const float* b_material = (const float*)d_in[5];
    const float* b_influx   = (const float*)d_in[6];
    const float* e_data     = (const float*)d_in[7];
    const float* W1         = (const float*)d_in[8];
    const float* b1         = (const float*)d_in[9];
    const float* W2         = (const float*)d_in[10];
    const float* b2         = (const float*)d_in[11];
    float* out = (float*)d_out;

    int E = in_sizes[0];

    prep_kernel<<<4, 128>>>(W1, b1, W2, b2);

    void* cp_addr = nullptr;
    void* scr_addr = nullptr;
    cudaGetSymbolAddress(&cp_addr, cP);
    cudaGetSymbolAddress(&scr_addr, dScratch);
    cudaMemcpyAsync(cp_addr, scr_addr, sizeof(CParams), cudaMemcpyDeviceToDevice, 0);

    long pairs = ((long)E + 1) / 2;
    int threads = 128;
    int blocks = (int)((pairs + threads - 1) / threads);
    edge_mlp_kernel<<<blocks, threads>>>(r, a_data, a_material, a_influx,
                                         b_data, b_material, b_influx, e_data,
                                         out, E);
}

// round 13
// speedup vs baseline: 1.0969x; 1.0969x over previous
#include <cuda_runtime.h>
#include <cstdint>

#define NUM_IN 25
#define NUM_OUT 20
#define J_PAIRS 13
#define I_PAIRS 10

typedef unsigned long long u64;

// Constant bank: all packed weights (constant port / LDC only).
struct __align__(16) CParams {
    u64 w1[25][14];  // [k][jp] = {W1[2jp][k], W1[2jp+1][k]}
    u64 b1[14];
    u64 w2[25][10];  // [k][ip] = {W2[2ip][k], W2[2ip+1][k]}
    u64 b2[10];
};
__constant__ CParams cP;

__device__ __forceinline__ u64 dpack(float lo, float hi) {
    return (u64)__float_as_uint(lo) | ((u64)__float_as_uint(hi) << 32);
}
__device__ __forceinline__ u64 pk2s(float v) {
    u64 r;
    asm("mov.b64 %0, {%1, %1};" : "=l"(r) : "f"(v));
    return r;
}
__device__ __forceinline__ void upk2(u64 v, float& lo, float& hi) {
    asm("mov.b64 {%0, %1}, %2;" : "=f"(lo), "=f"(hi) : "l"(v));
}
__device__ __forceinline__ u64 ffma2(u64 a, u64 b, u64 c) {
    u64 d;
    asm("fma.rn.f32x2 %0, %1, %2, %3;" : "=l"(d) : "l"(a), "l"(b), "l"(c));
    return d;
}

// ---- Prep: pack weights straight into cP's backing store (no memcpy node) ----
__global__ void prep_kernel(CParams* __restrict__ cp,
                            const float* __restrict__ W1, const float* __restrict__ b1,
                            const float* __restrict__ W2, const float* __restrict__ b2)
{
    int t = threadIdx.x;
    int stride = blockDim.x;
    for (int i = t; i < 25 * 14; i += stride) {
        int k = i / 14, jp = i % 14;
        float lo = 0.0f, hi = 0.0f;
        if (jp < J_PAIRS) {
            lo = W1[(2 * jp) * NUM_IN + k];
            if (2 * jp + 1 < NUM_IN) hi = W1[(2 * jp + 1) * NUM_IN + k];
        }
        cp->w1[k][jp] = dpack(lo, hi);
    }
    for (int i = t; i < 14; i += stride) {
        float lo = 0.0f, hi = 0.0f;
        if (i < J_PAIRS) {
            lo = b1[2 * i];
            if (2 * i + 1 < NUM_IN) hi = b1[2 * i + 1];
        }
        cp->b1[i] = dpack(lo, hi);
    }
    for (int i = t; i < 25 * 10; i += stride) {
        int k = i / 10, ip = i % 10;
        cp->w2[k][ip] = dpack(W2[(2 * ip) * NUM_IN + k], W2[(2 * ip + 1) * NUM_IN + k]);
    }
    for (int i = t; i < 10; i += stride)
        cp->b2[i] = dpack(b2[2 * i], b2[2 * i + 1]);
}

// Layer-1 partial over k in [K0,K1)
template <int K0, int K1>
__device__ __forceinline__ void l1_phase(const float (&xa0)[K1 - K0],
                                         const float (&xa1)[K1 - K0],
                                         u64 (&acc0)[J_PAIRS], u64 (&acc1)[J_PAIRS])
{
    #pragma unroll
    for (int k = K0; k < K1; k++) {
        u64 xk0 = pk2s(xa0[k - K0]);
        u64 xk1 = pk2s(xa1[k - K0]);
        const ulonglong2* wv = reinterpret_cast<const ulonglong2*>(cP.w1[k]);
        #pragma unroll
        for (int q = 0; q < 6; q++) {
            ulonglong2 w = wv[q];
            acc0[2 * q]     = ffma2(w.x, xk0, acc0[2 * q]);
            acc1[2 * q]     = ffma2(w.x, xk1, acc1[2 * q]);
            acc0[2 * q + 1] = ffma2(w.y, xk0, acc0[2 * q + 1]);
            acc1[2 * q + 1] = ffma2(w.y, xk1, acc1[2 * q + 1]);
        }
        u64 w12 = cP.w1[k][12];
        acc0[12] = ffma2(w12, xk0, acc0[12]);
        acc1[12] = ffma2(w12, xk1, acc1[12]);
    }
}

// ---- Main: 2 edges/thread, all weights via constant port (R10 structure) ----
__global__ void __launch_bounds__(128, 5)
edge_mlp_kernel(const float* __restrict__ r,
                const float* __restrict__ a_data,
                const float* __restrict__ a_material,
                const float* __restrict__ a_influx,
                const float* __restrict__ b_data,
                const float* __restrict__ b_material,
                const float* __restrict__ b_influx,
                const float* __restrict__ e_data,
                float* __restrict__ out,
                int E)
{
    long pair = (long)blockIdx.x * blockDim.x + threadIdx.x;
    long e0 = pair * 2;
    if (e0 >= E) return;
    bool have_e1 = (e0 + 1 < E);
    long e1 = have_e1 ? (e0 + 1) : e0;

    const float4* ad4 = reinterpret_cast<const float4*>(a_data);
    const float4* bd4 = reinterpret_cast<const float4*>(b_data);
    const float4* ed4 = reinterpret_cast<const float4*>(e_data);

    u64 acc0[J_PAIRS], acc1[J_PAIRS];
    #pragma unroll
    for (int p = 0; p < J_PAIRS; p++) { acc0[p] = cP.b1[p]; acc1[p] = cP.b1[p]; }

    // Phase A: features 0..10
    {
        float xa0[11], xa1[11];
        xa0[0] = r[e0]; xa1[0] = r[e1];
        {
            float4 p = ad4[2 * e0], q = ad4[2 * e1];
            xa0[1] = p.x; xa0[2] = p.y; xa0[3] = p.z; xa0[4] = p.w;
            xa1[1] = q.x; xa1[2] = q.y; xa1[3] = q.z; xa1[4] = q.w;
            p = ad4[2 * e0 + 1]; q = ad4[2 * e1 + 1];
            xa0[5] = p.x; xa0[6] = p.y; xa0[7] = p.z; xa0[8] = p.w;
            xa1[5] = q.x; xa1[6] = q.y; xa1[7] = q.z; xa1[8] = q.w;
        }
        xa0[9]  = a_material[e0]; xa1[9]  = a_material[e1];
        xa0[10] = a_influx[e0];   xa1[10] = a_influx[e1];
        l1_phase<0, 11>(xa0, xa1, acc0, acc1);
    }
    // Phase B: features 11..24
    {
        float xb0[14], xb1[14];
        {
            float4 p = bd4[2 * e0], q = bd4[2 * e1];
            xb0[0] = p.x; xb0[1] = p.y; xb0[2] = p.z; xb0[3] = p.w;
            xb1[0] = q.x; xb1[1] = q.y; xb1[2] = q.z; xb1[3] = q.w;
            p = bd4[2 * e0 + 1]; q = bd4[2 * e1 + 1];
            xb0[4] = p.x; xb0[5] = p.y; xb0[6] = p.z; xb0[7] = p.w;
            xb1[4] = q.x; xb1[5] = q.y; xb1[6] = q.z; xb1[7] = q.w;
        }
        xb0[8] = b_material[e0]; xb1[8] = b_material[e1];
        xb0[9] = b_influx[e0];   xb1[9] = b_influx[e1];
        {
            float4 p = ed4[e0], q = ed4[e1];
            xb0[10] = p.x; xb0[11] = p.y; xb0[12] = p.z; xb0[13] = p.w;
            xb1[10] = q.x; xb1[11] = q.y; xb1[12] = q.z; xb1[13] = q.w;
        }
        l1_phase<11, 25>(xb0, xb1, acc0, acc1);
    }

    // ReLU -> y
    float y0[2 * J_PAIRS], y1[2 * J_PAIRS];
    #pragma unroll
    for (int p = 0; p < J_PAIRS; p++) {
        float lo, hi;
        upk2(acc0[p], lo, hi);
        y0[2 * p]     = fmaxf(lo, 0.0f);
        y0[2 * p + 1] = fmaxf(hi, 0.0f);
        upk2(acc1[p], lo, hi);
        y1[2 * p]     = fmaxf(lo, 0.0f);
        y1[2 * p + 1] = fmaxf(hi, 0.0f);
    }

    // Layer 2: single pass, constant-port weights
    u64 z0[I_PAIRS], z1[I_PAIRS];
    #pragma unroll
    for (int p = 0; p < I_PAIRS; p++) { z0[p] = cP.b2[p]; z1[p] = cP.b2[p]; }

    #pragma unroll
    for (int k = 0; k < NUM_IN; k++) {
        u64 yk0 = pk2s(y0[k]);
        u64 yk1 = pk2s(y1[k]);
        const ulonglong2* wv = reinterpret_cast<const ulonglong2*>(cP.w2[k]);
        #pragma unroll
        for (int q = 0; q < 5; q++) {
            ulonglong2 w = wv[q];
            z0[2 * q]     = ffma2(w.x, yk0, z0[2 * q]);
            z1[2 * q]     = ffma2(w.x, yk1, z1[2 * q]);
            z0[2 * q + 1] = ffma2(w.y, yk0, z0[2 * q + 1]);
            z1[2 * q + 1] = ffma2(w.y, yk1, z1[2 * q + 1]);
        }
    }

    float zl[NUM_OUT], zh[NUM_OUT];
    #pragma unroll
    for (int p = 0; p < I_PAIRS; p++) {
        float lo, hi;
        upk2(z0[p], lo, hi);
        zl[2 * p]     = fmaxf(lo, 0.0f);
        zl[2 * p + 1] = fmaxf(hi, 0.0f);
        upk2(z1[p], lo, hi);
        zh[2 * p]     = fmaxf(lo, 0.0f);
        zh[2 * p + 1] = fmaxf(hi, 0.0f);
    }

    // Scatter to the three concatenated output blocks
    float4* ov = reinterpret_cast<float4*>(out);
    long Ef4_b1 = 2L * (long)E;
    long Ef4_b2 = 4L * (long)E;

    ov[2 * e0]              = make_float4(zl[0],  zl[1],  zl[2],  zl[3]);
    ov[2 * e0 + 1]          = make_float4(zl[4],  zl[5],  zl[6],  zl[7]);
    ov[Ef4_b1 + 2 * e0]     = make_float4(zl[8],  zl[9],  zl[10], zl[11]);
    ov[Ef4_b1 + 2 * e0 + 1] = make_float4(zl[12], zl[13], zl[14], zl[15]);
    ov[Ef4_b2 + e0]         = make_float4(zl[16], zl[17], zl[18], zl[19]);

    if (have_e1) {
        ov[2 * e1]              = make_float4(zh[0],  zh[1],  zh[2],  zh[3]);
        ov[2 * e1 + 1]          = make_float4(zh[4],  zh[5],  zh[6],  zh[7]);
        ov[Ef4_b1 + 2 * e1]     = make_float4(zh[8],  zh[9],  zh[10], zh[11]);
        ov[Ef4_b1 + 2 * e1 + 1] = make_float4(zh[12], zh[13], zh[14], zh[15]);
        ov[Ef4_b2 + e1]         = make_float4(zh[16], zh[17], zh[18], zh[19]);
    }
}

extern "C" void kernel_launch(void* const* d_in, const int* in_sizes, int n_in,
                              void* d_out, int out_size)
{
    const float* r          = (const float*)d_in[0];
    const float* a_data     = (const float*)d_in[1];
    const float* a_material = (const float*)d_in[2];
    const float* a_influx   = (const float*)d_in[3];
    const float* b_data     = (const float*)d_in[4];
    const float* b_material = (const float*)d_in[5];
    const float* b_influx   = (const float*)d_in[6];
    const float* e_data     = (const float*)d_in[7];
    const float* W1         = (const float*)d_in[8];
    const float* b1         = (const float*)d_in[9];
    const float* W2         = (const float*)d_in[10];
    const float* b2         = (const float*)d_in[11];
    float* out = (float*)d_out;

    int E = in_sizes[0];

    // Prep writes packed weights directly into cP's backing store.
    // (Const cache is invalidated at each launch boundary, so the main
    //  kernel's LDC reads see the fresh data.)
    void* cp_addr = nullptr;
    cudaGetSymbolAddress(&cp_addr, cP);
    prep_kernel<<<1, 256>>>((CParams*)cp_addr, W1, b1, W2, b2);

    long pairs = ((long)E + 1) / 2;
    int threads = 128;
    int blocks = (int)((pairs + threads - 1) / threads);
    edge_mlp_kernel<<<blocks, threads>>>(r, a_data, a_material, a_influx,
                                         b_data, b_material, b_influx, e_data,
                                         out, E);
}